// round 17
// baseline (speedup 1.0000x reference)
#include <cuda_runtime.h>
#include <cuda_bf16.h>
#include <cuda_fp16.h>
#include <cstdint>
#include <math.h>

#define BB 16
#define CC 512
#define LL 1024       // h*w
#define GG 8
#define CPG 64        // channels per group
#define NH 4
#define HD 128
#define EPS_GN 1e-5f
#define QK_SCALE 0.08838834764831845f

// ---------------------------------------------------------------------------
// Scratch (device globals: no allocation allowed) — all fp16 single plane
// ---------------------------------------------------------------------------
__device__ __half g_xnT [(size_t)BB*LL*CC];               // xn^T  [b][l][c]
__device__ __half g_attT[(size_t)BB*LL*CC];               // att^T [b][l][c]
__device__ __half g_wq[(size_t)3*CC*CC];
__device__ __half g_wp[(size_t)CC*CC];
__device__ __half g_qt[(size_t)BB*NH*LL*HD];              // [b][h][l][d] (scaled)
__device__ __half g_kt[(size_t)BB*NH*LL*HD];              // [b][h][l][d]
__device__ __half g_v [(size_t)BB*NH*HD*LL];              // [b][h][d][l]
__device__ float g_mean[BB*GG];
__device__ float g_rstd[BB*GG];

// ---------------------------------------------------------------------------
// helpers
// ---------------------------------------------------------------------------
__device__ __forceinline__ uint32_t smem_u32(const void* p) {
    uint32_t a;
    asm("{ .reg .u64 t; cvta.to.shared.u64 t, %1; cvt.u32.u64 %0, t; }" : "=r"(a) : "l"(p));
    return a;
}
__device__ __forceinline__ void mma16816h(float* c, const uint32_t* a, const uint32_t* b) {
    asm volatile(
        "mma.sync.aligned.m16n8k16.row.col.f32.f16.f16.f32 "
        "{%0,%1,%2,%3}, {%4,%5,%6,%7}, {%8,%9}, {%0,%1,%2,%3};"
        : "+f"(c[0]), "+f"(c[1]), "+f"(c[2]), "+f"(c[3])
        : "r"(a[0]), "r"(a[1]), "r"(a[2]), "r"(a[3]), "r"(b[0]), "r"(b[1]));
}
__device__ __forceinline__ void ldm4(uint32_t* r, uint32_t a) {
    asm volatile("ldmatrix.sync.aligned.m8n8.x4.shared.b16 {%0,%1,%2,%3}, [%4];"
        : "=r"(r[0]), "=r"(r[1]), "=r"(r[2]), "=r"(r[3]) : "r"(a));
}
__device__ __forceinline__ uint32_t packh2(float a, float b) {
    __half2 t = __floats2half2_rn(a, b);
    return *(uint32_t*)&t;
}
__device__ __forceinline__ void cp16(uint32_t s, const void* g) {
    asm volatile("cp.async.cg.shared.global [%0], [%1], 16;" :: "r"(s), "l"(g) : "memory");
}
#define CP_COMMIT() asm volatile("cp.async.commit_group;" ::: "memory")
#define CP_WAIT0()  asm volatile("cp.async.wait_group 0;" ::: "memory")

// ---------------------------------------------------------------------------
// GroupNorm statistics
// ---------------------------------------------------------------------------
__global__ void __launch_bounds__(512) gn_stats_kernel(const float* __restrict__ x) {
    int bg = blockIdx.x;
    int b = bg / GG, g = bg % GG;
    const float4* p = (const float4*)(x + ((size_t)b*CC + (size_t)g*CPG) * LL);
    const int n4 = CPG * LL / 4;
    float s = 0.f, sq = 0.f;
    for (int i = threadIdx.x; i < n4; i += 512) {
        float4 v = p[i];
        s  += v.x + v.y + v.z + v.w;
        sq += v.x*v.x + v.y*v.y + v.z*v.z + v.w*v.w;
    }
    __shared__ float ss[512], sq_s[512];
    ss[threadIdx.x] = s; sq_s[threadIdx.x] = sq;
    __syncthreads();
    for (int o = 256; o > 0; o >>= 1) {
        if (threadIdx.x < o) { ss[threadIdx.x] += ss[threadIdx.x+o]; sq_s[threadIdx.x] += sq_s[threadIdx.x+o]; }
        __syncthreads();
    }
    if (threadIdx.x == 0) {
        const float invN = 1.0f / (float)(CPG * LL);
        float mean = ss[0] * invN;
        float var  = sq_s[0] * invN - mean * mean;
        g_mean[bg] = mean;
        g_rstd[bg] = rsqrtf(var + EPS_GN);
    }
}

// ---------------------------------------------------------------------------
// GroupNorm apply + transpose + fp16: x[b][c][l] -> xnT[b][l][c]
// ---------------------------------------------------------------------------
__global__ void __launch_bounds__(256) gn_norm_t_kernel(const float* __restrict__ x,
                                                        const float* __restrict__ gamma,
                                                        const float* __restrict__ beta) {
    const int b  = blockIdx.z;
    const int c0 = blockIdx.y * 64;
    const int l0 = blockIdx.x * 64;
    const int gidx = b * GG + c0 / CPG;
    const float mean = g_mean[gidx], rstd = g_rstd[gidx];

    __shared__ float t[64][65];
    for (int idx = threadIdx.x; idx < 1024; idx += 256) {
        int i  = idx >> 4;
        int j4 = (idx & 15) * 4;
        int c = c0 + i;
        float ga = gamma[c] * rstd;
        float be = beta[c] - mean * ga;
        float4 v = *(const float4*)(x + ((size_t)b*CC + c)*LL + l0 + j4);
        t[j4+0][i] = v.x*ga + be; t[j4+1][i] = v.y*ga + be;
        t[j4+2][i] = v.z*ga + be; t[j4+3][i] = v.w*ga + be;
    }
    __syncthreads();
    for (int idx = threadIdx.x; idx < 1024; idx += 256) {
        int l  = idx >> 4;
        int cq = (idx & 15) * 4;
        uint32_t w[2];
        w[0] = packh2(t[l][cq + 0], t[l][cq + 1]);
        w[1] = packh2(t[l][cq + 2], t[l][cq + 3]);
        size_t o = ((size_t)b*LL + l0 + l) * CC + c0 + cq;
        *(uint2*)(g_xnT + o) = *(uint2*)w;
    }
}

// ---------------------------------------------------------------------------
// Weight fp32 -> fp16 convert (both weights, one launch)
// ---------------------------------------------------------------------------
__global__ void __launch_bounds__(256) convert2_kernel(
        const float* __restrict__ a, __half* __restrict__ da, int na,
        const float* __restrict__ b, __half* __restrict__ db, int nb) {
    int i = blockIdx.x * 256 + threadIdx.x;
    if (i < na)             da[i] = __float2half(a[i]);
    else if (i - na < nb)   db[i - na] = __float2half(b[i - na]);
}

// ---------------------------------------------------------------------------
// Fused QKV GEMM (fp16 1-term mma.sync, cp.async, ldmatrix) + conversion
//   epilogue.  role by blockIdx.y: 0-3 Q(head y), 4-7 K, 8-11 V
//   2 CTAs/SM: smem 40 KB (transpose done in two 64-d passes)
// ---------------------------------------------------------------------------
#define TILE_B 10240          // 128 rows x 80B (64B fp16 data + 16 pad)
#define STAGE_B 20480         // 2 tiles: A, B
__global__ void __launch_bounds__(256, 2) gemm_qkv_kernel(
        const __half* __restrict__ A, const __half* __restrict__ B_all,
        const float* __restrict__ bias) {
    extern __shared__ char smc[];
    const uint32_t sbase = smem_u32(smc);
    const int tid = threadIdx.x;
    const int wid = tid >> 5;
    const int lane = tid & 31;
    const int g  = lane >> 2;
    const int tg = lane & 3;
    const int wm = wid >> 2;
    const int wn = wid & 3;
    const int b  = blockIdx.z;
    const int m0 = blockIdx.y * 128;
    const int n0 = blockIdx.x * 128;
    const int K  = CC;

    const __half* B = B_all + (size_t)b * LL * CC;

    auto load_chunk = [&](int k0, int stage) {
        uint32_t st = sbase + stage * STAGE_B;
        #pragma unroll
        for (int i = 0; i < 4; i++) {
            int idx = tid + i * 256;            // 0..1023
            int t = idx >> 9;                   // 0 A / 1 B
            int r = (idx >> 2) & 127;
            int u = idx & 3;
            const __half* src = (t ? B + (size_t)(n0 + r) * K
                                   : A + (size_t)(m0 + r) * K) + k0 + u * 8;
            cp16(st + t * TILE_B + r * 80 + u * 16, src);
        }
    };

    const uint32_t aOff = (uint32_t)(wm * 64 + (lane & 15)) * 80 + ((lane >> 4) << 4);
    const uint32_t bOff = (uint32_t)(wn * 32 + (lane & 7) + ((lane >> 4) << 3)) * 80
                        + (((lane >> 3) & 1) << 4);

    float acc[4][4][4];
    #pragma unroll
    for (int i = 0; i < 4; i++)
        #pragma unroll
        for (int j = 0; j < 4; j++)
            #pragma unroll
            for (int q = 0; q < 4; q++) acc[i][j][q] = 0.f;

    load_chunk(0, 0);
    CP_COMMIT();

    const int NCH = K / 32;
    for (int c = 0; c < NCH; c++) {
        CP_WAIT0();
        __syncthreads();
        if (c + 1 < NCH) { load_chunk((c + 1) * 32, (c + 1) & 1); CP_COMMIT(); }

        const uint32_t st = sbase + (c & 1) * STAGE_B;
        #pragma unroll
        for (int kk = 0; kk < 2; kk++) {
            const uint32_t kb = kk * 32;
            uint32_t bf[2][4];
            ldm4(bf[0], st + TILE_B + bOff + kb);
            ldm4(bf[1], st + TILE_B + bOff + 16 * 80 + kb);
            #pragma unroll
            for (int mt = 0; mt < 4; mt++) {
                uint32_t a4[4];
                ldm4(a4, st + aOff + mt * 16 * 80 + kb);
                #pragma unroll
                for (int nt = 0; nt < 4; nt++)
                    mma16816h(acc[mt][nt], a4, bf[nt >> 1] + (nt & 1) * 2);
            }
        }
        __syncthreads();
    }

    // ---- conversion epilogue ----
    const int role = blockIdx.y >> 2;       // 0 q, 1 k, 2 v
    const int h    = blockIdx.y & 3;
    const float scale = (role == 0) ? QK_SCALE : 1.f;

    if (role == 2) {
        // V: direct fp16 store, [b][h][d(=row)][l]
        #pragma unroll
        for (int mt = 0; mt < 4; mt++) {
            int d0 = wm * 64 + mt * 16 + g;
            int d1 = d0 + 8;
            float bv0 = bias[m0 + d0], bv1 = bias[m0 + d1];
            #pragma unroll
            for (int nt = 0; nt < 4; nt++) {
                int col = n0 + wn * 32 + nt * 8 + tg * 2;
                size_t o0 = ((size_t)(b * NH + h) * HD + d0) * LL + col;
                *(uint32_t*)(g_v + o0) = packh2(acc[mt][nt][0] + bv0, acc[mt][nt][1] + bv0);
                size_t o1 = ((size_t)(b * NH + h) * HD + d1) * LL + col;
                *(uint32_t*)(g_v + o1) = packh2(acc[mt][nt][2] + bv1, acc[mt][nt][3] + bv1);
            }
        }
        return;
    }

    // Q/K: transpose in TWO passes over 64-d halves (ts: 128 l-rows x 68 floats)
    float* ts = (float*)smc;
    __half* dh = (role == 0 ? g_qt : g_kt) + (size_t)(b * NH + h) * LL * HD;
    #pragma unroll
    for (int p = 0; p < 2; p++) {
        if (wm == p) {
            #pragma unroll
            for (int mt = 0; mt < 4; mt++) {
                int d0l = mt * 16 + g;          // local d within 64-half
                int d1l = d0l + 8;
                float bv0 = bias[m0 + p * 64 + d0l];
                float bv1 = bias[m0 + p * 64 + d1l];
                #pragma unroll
                for (int nt = 0; nt < 4; nt++) {
                    int col = wn * 32 + nt * 8 + tg * 2;
                    ts[(col + 0) * 68 + d0l] = (acc[mt][nt][0] + bv0) * scale;
                    ts[(col + 1) * 68 + d0l] = (acc[mt][nt][1] + bv0) * scale;
                    ts[(col + 0) * 68 + d1l] = (acc[mt][nt][2] + bv1) * scale;
                    ts[(col + 1) * 68 + d1l] = (acc[mt][nt][3] + bv1) * scale;
                }
            }
        }
        __syncthreads();
        {
            int l  = tid >> 1;                  // 0..127
            int dl = (tid & 1) * 32;
            #pragma unroll
            for (int i = 0; i < 4; i++) {
                float4 v0 = *(const float4*)&ts[l * 68 + dl + i * 8];
                float4 v1 = *(const float4*)&ts[l * 68 + dl + i * 8 + 4];
                uint32_t w[4];
                w[0] = packh2(v0.x, v0.y); w[1] = packh2(v0.z, v0.w);
                w[2] = packh2(v1.x, v1.y); w[3] = packh2(v1.z, v1.w);
                size_t o = (size_t)(n0 + l) * HD + p * 64 + dl + i * 8;
                *(uint4*)(dh + o) = *(uint4*)w;
            }
        }
        __syncthreads();
    }
}

// ---------------------------------------------------------------------------
// Proj GEMM (fp16 1-term) + bias + residual, fp32 out — 2 CTAs/SM
// ---------------------------------------------------------------------------
__global__ void __launch_bounds__(256, 2) gemm_proj_kernel(
        const __half* __restrict__ A, const __half* __restrict__ B_all,
        const float* __restrict__ bias, const float* __restrict__ res,
        float* __restrict__ out) {
    extern __shared__ char smc[];
    const uint32_t sbase = smem_u32(smc);
    const int tid = threadIdx.x;
    const int wid = tid >> 5;
    const int lane = tid & 31;
    const int g  = lane >> 2;
    const int tg = lane & 3;
    const int wm = wid >> 2;
    const int wn = wid & 3;
    const int b  = blockIdx.z;
    const int m0 = blockIdx.y * 128;
    const int n0 = blockIdx.x * 128;
    const int K  = CC;
    const int M  = CC;

    const __half* B = B_all + (size_t)b * LL * CC;

    auto load_chunk = [&](int k0, int stage) {
        uint32_t st = sbase + stage * STAGE_B;
        #pragma unroll
        for (int i = 0; i < 4; i++) {
            int idx = tid + i * 256;
            int t = idx >> 9;
            int r = (idx >> 2) & 127;
            int u = idx & 3;
            const __half* src = (t ? B + (size_t)(n0 + r) * K
                                   : A + (size_t)(m0 + r) * K) + k0 + u * 8;
            cp16(st + t * TILE_B + r * 80 + u * 16, src);
        }
    };

    const uint32_t aOff = (uint32_t)(wm * 64 + (lane & 15)) * 80 + ((lane >> 4) << 4);
    const uint32_t bOff = (uint32_t)(wn * 32 + (lane & 7) + ((lane >> 4) << 3)) * 80
                        + (((lane >> 3) & 1) << 4);

    float acc[4][4][4];
    #pragma unroll
    for (int i = 0; i < 4; i++)
        #pragma unroll
        for (int j = 0; j < 4; j++)
            #pragma unroll
            for (int q = 0; q < 4; q++) acc[i][j][q] = 0.f;

    load_chunk(0, 0);
    CP_COMMIT();

    const int NCH = K / 32;
    for (int c = 0; c < NCH; c++) {
        CP_WAIT0();
        __syncthreads();
        if (c + 1 < NCH) { load_chunk((c + 1) * 32, (c + 1) & 1); CP_COMMIT(); }

        const uint32_t st = sbase + (c & 1) * STAGE_B;
        #pragma unroll
        for (int kk = 0; kk < 2; kk++) {
            const uint32_t kb = kk * 32;
            uint32_t bf[2][4];
            ldm4(bf[0], st + TILE_B + bOff + kb);
            ldm4(bf[1], st + TILE_B + bOff + 16 * 80 + kb);
            #pragma unroll
            for (int mt = 0; mt < 4; mt++) {
                uint32_t a4[4];
                ldm4(a4, st + aOff + mt * 16 * 80 + kb);
                #pragma unroll
                for (int nt = 0; nt < 4; nt++)
                    mma16816h(acc[mt][nt], a4, bf[nt >> 1] + (nt & 1) * 2);
            }
        }
        __syncthreads();
    }

    #pragma unroll
    for (int mt = 0; mt < 4; mt++) {
        int r0 = m0 + wm * 64 + mt * 16 + g;
        int r1 = r0 + 8;
        float bv0 = bias[r0], bv1 = bias[r1];
        #pragma unroll
        for (int nt = 0; nt < 4; nt++) {
            int col = n0 + wn * 32 + nt * 8 + tg * 2;
            size_t off0 = ((size_t)b * M + r0) * LL + col;
            size_t off1 = ((size_t)b * M + r1) * LL + col;
            float2 q0 = *(const float2*)(res + off0);
            float2 q1 = *(const float2*)(res + off1);
            float2 o0 = make_float2(acc[mt][nt][0] + bv0 + q0.x, acc[mt][nt][1] + bv0 + q0.y);
            float2 o1 = make_float2(acc[mt][nt][2] + bv1 + q1.x, acc[mt][nt][3] + bv1 + q1.y);
            *(float2*)(out + off0) = o0;
            *(float2*)(out + off1) = o1;
        }
    }
}

// ---------------------------------------------------------------------------
// Flash attention, fp16 MMAs, register softmax, Q fragments hoisted.
// CTA = (64 q-rows, h, b), 128 threads (4 warps); warp owns 16 q-rows.
// smem 89088 -> 2 CTAs/SM.
// ---------------------------------------------------------------------------
#define QSTR 272     // 256B row + 16 pad
#define VSTR 144     // 128B row + 16 pad
#define AQ_OFF 0                    // Q 64x272 = 17408
#define AK_OFF 17408                // stage: 17408  x2
#define AV_OFF 52224                // stage: 18432  x2
#define ATTN_SMEM 89088

__global__ void __launch_bounds__(128) attn_mma_kernel() {
    extern __shared__ char smc[];
    const uint32_t sbase = smem_u32(smc);
    const int tid = threadIdx.x;
    const int wid = tid >> 5;           // 0..3
    const int lane = tid & 31;
    const int g  = lane >> 2;
    const int tg = lane & 3;
    const int lq0 = blockIdx.x * 64;
    const int h   = blockIdx.y;
    const int b   = blockIdx.z;
    const int wq0 = wid * 16;

    const size_t bh_ld = (size_t)(b * NH + h) * LL * HD;
    const __half* qt = g_qt + bh_ld + (size_t)lq0 * HD;
    const __half* kt = g_kt + bh_ld;
    const __half* vp = g_v + bh_ld;              // [d][l]

    auto load_kv = [&](int lk0, int s) {
        uint32_t kb = sbase + AK_OFF + s * 17408;
        uint32_t vb = sbase + AV_OFF + s * 18432;
        #pragma unroll
        for (int i = 0; i < 8; i++) {
            int idx = tid + i * 128;                 // 0..1023
            int r = idx >> 4, u = idx & 15;
            cp16(kb + r * QSTR + u * 16, kt + (size_t)(lk0 + r) * HD + u * 8);
        }
        #pragma unroll
        for (int i = 0; i < 8; i++) {
            int idx = tid + i * 128;
            int r = idx >> 3, u = idx & 7;
            cp16(vb + r * VSTR + u * 16, vp + (size_t)r * LL + lk0 + u * 8);
        }
    };

    // initial group: Q (64 rows) + K/V stage 0
    #pragma unroll
    for (int i = 0; i < 8; i++) {
        int idx = tid + i * 128;                     // 0..1023
        int r = idx >> 4, u = idx & 15;
        cp16(sbase + AQ_OFF + r * QSTR + u * 16, qt + (size_t)r * HD + u * 8);
    }
    load_kv(0, 0);
    CP_COMMIT();

    const uint32_t qOff = (uint32_t)(wq0 + (lane & 15)) * QSTR + ((lane >> 4) << 4);
    const uint32_t kOff = (uint32_t)((lane & 7) + ((lane >> 4) << 3)) * QSTR
                        + (((lane >> 3) & 1) << 4);
    const uint32_t vOff = (uint32_t)((lane & 7) + ((lane >> 4) << 3)) * VSTR
                        + (((lane >> 3) & 1) << 4);

    CP_WAIT0();
    __syncthreads();

    // hoist Q fragments (iteration-invariant)
    uint32_t qa[8][4];
    #pragma unroll
    for (int ks = 0; ks < 8; ks++)
        ldm4(qa[ks], sbase + AQ_OFF + qOff + ks * 32);

    load_kv(64, 1);
    CP_COMMIT();

    float rm0 = -1e30f, rm1 = -1e30f, rs0 = 0.f, rs1 = 0.f;
    float accO[16][4];
    #pragma unroll
    for (int i = 0; i < 16; i++)
        #pragma unroll
        for (int q = 0; q < 4; q++) accO[i][q] = 0.f;

    for (int it = 0; it < 16; it++) {
        const int st = it & 1;

        // ---- S = Q K^T (fp16), warp tile 16q x 64k ----
        float accS[8][4];
        #pragma unroll
        for (int i = 0; i < 8; i++)
            #pragma unroll
            for (int q = 0; q < 4; q++) accS[i][q] = 0.f;
        {
            const uint32_t KA = sbase + AK_OFF + st * 17408;
            #pragma unroll
            for (int ks = 0; ks < 8; ks++) {
                const uint32_t kb = ks * 32;
                #pragma unroll
                for (int p = 0; p < 4; p++) {
                    uint32_t k4[4];
                    ldm4(k4, KA + kOff + p * 16 * QSTR + kb);
                    mma16816h(accS[p*2+0], qa[ks], k4);
                    mma16816h(accS[p*2+1], qa[ks], k4 + 2);
                }
            }
        }

        // ---- online softmax, fully in registers (rows g, g+8) ----
        float m0 = -1e30f, m1 = -1e30f;
        #pragma unroll
        for (int nt = 0; nt < 8; nt++) {
            m0 = fmaxf(m0, fmaxf(accS[nt][0], accS[nt][1]));
            m1 = fmaxf(m1, fmaxf(accS[nt][2], accS[nt][3]));
        }
        m0 = fmaxf(m0, __shfl_xor_sync(0xffffffff, m0, 1));
        m0 = fmaxf(m0, __shfl_xor_sync(0xffffffff, m0, 2));
        m1 = fmaxf(m1, __shfl_xor_sync(0xffffffff, m1, 1));
        m1 = fmaxf(m1, __shfl_xor_sync(0xffffffff, m1, 2));
        float nm0 = fmaxf(rm0, m0), nm1 = fmaxf(rm1, m1);
        float al0 = __expf(rm0 - nm0), al1 = __expf(rm1 - nm1);
        rm0 = nm0; rm1 = nm1;

        uint32_t pa[4][4];
        float s0 = 0.f, s1 = 0.f;
        #pragma unroll
        for (int kk = 0; kk < 4; kk++) {
            float p00 = __expf(accS[2*kk][0] - nm0);
            float p01 = __expf(accS[2*kk][1] - nm0);
            float p10 = __expf(accS[2*kk][2] - nm1);
            float p11 = __expf(accS[2*kk][3] - nm1);
            float q00 = __expf(accS[2*kk+1][0] - nm0);
            float q01 = __expf(accS[2*kk+1][1] - nm0);
            float q10 = __expf(accS[2*kk+1][2] - nm1);
            float q11 = __expf(accS[2*kk+1][3] - nm1);
            s0 += p00 + p01 + q00 + q01;
            s1 += p10 + p11 + q10 + q11;
            pa[kk][0] = packh2(p00, p01);
            pa[kk][1] = packh2(p10, p11);
            pa[kk][2] = packh2(q00, q01);
            pa[kk][3] = packh2(q10, q11);
        }
        s0 += __shfl_xor_sync(0xffffffff, s0, 1);
        s0 += __shfl_xor_sync(0xffffffff, s0, 2);
        s1 += __shfl_xor_sync(0xffffffff, s1, 1);
        s1 += __shfl_xor_sync(0xffffffff, s1, 2);
        rs0 = rs0 * al0 + s0;
        rs1 = rs1 * al1 + s1;

        #pragma unroll
        for (int nt = 0; nt < 16; nt++) {
            accO[nt][0] *= al0; accO[nt][1] *= al0;
            accO[nt][2] *= al1; accO[nt][3] *= al1;
        }

        // ---- O += P V (fp16), warp tile 16q x 128d ----
        {
            const uint32_t VA = sbase + AV_OFF + st * 18432;
            #pragma unroll
            for (int kk = 0; kk < 4; kk++) {
                const uint32_t kb = kk * 32;
                #pragma unroll
                for (int p = 0; p < 8; p++) {
                    uint32_t v4[4];
                    ldm4(v4, VA + vOff + p * 16 * VSTR + kb);
                    mma16816h(accO[p*2+0], pa[kk], v4);
                    mma16816h(accO[p*2+1], pa[kk], v4 + 2);
                }
            }
        }

        // pipeline: wait next stage, then prefetch it+2 into current stage
        if (it + 1 < 16) {
            CP_WAIT0();
            __syncthreads();
            if (it + 2 < 16) { load_kv((it + 2) * 64, st); CP_COMMIT(); }
        }
    }

    // ---- epilogue: normalize, store att^T[b][l][c] fp16 ----
    float inv0 = 1.0f / rs0, inv1 = 1.0f / rs1;
    int ra = lq0 + wq0 + g, rb = ra + 8;
    #pragma unroll
    for (int nt = 0; nt < 16; nt++) {
        int dcol = h * HD + nt * 8 + tg * 2;
        size_t oa = ((size_t)b * LL + ra) * CC + dcol;
        *(uint32_t*)(g_attT + oa) = packh2(accO[nt][0] * inv0, accO[nt][1] * inv0);
        size_t ob = ((size_t)b * LL + rb) * CC + dcol;
        *(uint32_t*)(g_attT + ob) = packh2(accO[nt][2] * inv1, accO[nt][3] * inv1);
    }
}

// ---------------------------------------------------------------------------
extern "C" void kernel_launch(void* const* d_in, const int* in_sizes, int n_in,
                              void* d_out, int out_size) {
    const float* x      = (const float*)d_in[0];
    const float* gamma  = (const float*)d_in[1];
    const float* beta   = (const float*)d_in[2];
    const float* w_qkv  = (const float*)d_in[3];
    const float* b_qkv  = (const float*)d_in[4];
    const float* w_proj = (const float*)d_in[5];
    const float* b_proj = (const float*)d_in[6];
    float* out = (float*)d_out;

    __half *xnT, *attT, *wq, *wp;
    cudaGetSymbolAddress((void**)&xnT, g_xnT);
    cudaGetSymbolAddress((void**)&attT, g_attT);
    cudaGetSymbolAddress((void**)&wq, g_wq);
    cudaGetSymbolAddress((void**)&wp, g_wp);

    // weight converts + GN
    const int nwq = 3*CC*CC, nwp = CC*CC;
    convert2_kernel<<<(nwq + nwp + 255)/256, 256>>>(w_qkv, wq, nwq, w_proj, wp, nwp);
    gn_stats_kernel<<<BB*GG, 512>>>(x);
    gn_norm_t_kernel<<<dim3(LL/64, CC/64, BB), 256>>>(x, gamma, beta);

    // Fused QKV projection + conversion epilogue (smem 40 KB, 2 CTAs/SM)
    const int qkv_smem = 2 * STAGE_B;
    cudaFuncSetAttribute(gemm_qkv_kernel, cudaFuncAttributeMaxDynamicSharedMemorySize, qkv_smem);
    gemm_qkv_kernel<<<dim3(LL/128, 12, BB), 256, qkv_smem>>>(wq, xnT, b_qkv);

    // attention (fp16 mma.sync, register softmax, 2 CTAs/SM)
    cudaFuncSetAttribute(attn_mma_kernel, cudaFuncAttributeMaxDynamicSharedMemorySize, ATTN_SMEM);
    attn_mma_kernel<<<dim3(LL/64, NH, BB), 128, ATTN_SMEM>>>();

    // Output projection + residual (2 CTAs/SM)
    const int proj_smem = 2 * STAGE_B;
    cudaFuncSetAttribute(gemm_proj_kernel, cudaFuncAttributeMaxDynamicSharedMemorySize, proj_smem);
    gemm_proj_kernel<<<dim3(LL/128, CC/128, BB), 256, proj_smem>>>(
        wp, attT, b_proj, x, out);
}